// round 13
// baseline (speedup 1.0000x reference)
#include <cuda_runtime.h>
#include <math_constants.h>

typedef unsigned long long ull;

namespace {
constexpr int B_   = 32;
constexpr int P_   = 197;
constexpr int D_   = 768;
constexpr int H_   = 12;
constexpr int HD_  = 64;
constexpr int PPR  = 49;    // rep tokens per reference sample
constexpr int NREF = 16;    // int(B * 0.5)
constexpr int NF   = 784;   // NREF * PPR
constexpr int PT   = 12;    // rows per block in k_align
constexpr int NT   = (P_ + PT - 1) / PT;   // 17
constexpr int PTA  = 16;    // rows per block in k_attn
constexpr int NTA  = (P_ + PTA - 1) / PTA; // 13
constexpr float NEGF = -1e30f;
}

// scratch (device globals; no allocation allowed)
__device__ float g_qh  [B_ * H_ * P_ * HD_];
__device__ float g_khT [B_ * H_ * HD_ * P_];   // [b][h][c][p]
__device__ float g_vh  [B_ * H_ * P_ * HD_];
__device__ float g_vsum[B_ * H_ * P_ * HD_];
__device__ float g_rep [H_ * NF * HD_];        // [h][j][c]
__device__ float g_repT[H_ * HD_ * NF];        // [h][c][j]

// ---- packed f32x2 helpers (sm_103a) --------------------------------------
__device__ __forceinline__ ull pack2(float x, float y) {
    ull r; asm("mov.b64 %0, {%1, %2};" : "=l"(r) : "f"(x), "f"(y)); return r;
}
__device__ __forceinline__ ull fma2(ull a, ull b, ull c) {
    ull d; asm("fma.rn.f32x2 %0, %1, %2, %3;" : "=l"(d) : "l"(a), "l"(b), "l"(c));
    return d;
}
__device__ __forceinline__ void unpack2(ull p, float& x, float& y) {
    asm("mov.b64 {%0, %1}, %2;" : "=f"(x), "=f"(y) : "l"(p));
}
__device__ __forceinline__ ull lo2(const float4& v) {
    ull r; asm("mov.b64 %0, {%1, %2};" : "=l"(r) : "f"(v.x), "f"(v.y)); return r;
}
__device__ __forceinline__ ull hi2(const float4& v) {
    ull r; asm("mov.b64 %0, {%1, %2};" : "=l"(r) : "f"(v.z), "f"(v.w)); return r;
}

// ---------------------------------------------------------------------------
// Kernel 1: RMSNorm (over D=768) + head split. K written transposed.
// ---------------------------------------------------------------------------
__global__ __launch_bounds__(256) void k_rms(
    const float* __restrict__ q, const float* __restrict__ k,
    const float* __restrict__ v, const float* __restrict__ wq,
    const float* __restrict__ wk, const float* __restrict__ wv)
{
    int bp = blockIdx.x;
    int b = bp / P_;
    int p = bp % P_;
    int tid = threadIdx.x;
    int lane = tid & 31, warp = tid >> 5;
    size_t off = (size_t)bp * D_;

    float xq[3], xk[3], xv[3];
    float sq = 0.f, sk = 0.f, sv = 0.f;
#pragma unroll
    for (int i = 0; i < 3; i++) {
        int j = tid + i * 256;
        xq[i] = q[off + j]; sq += xq[i] * xq[i];
        xk[i] = k[off + j]; sk += xk[i] * xk[i];
        xv[i] = v[off + j]; sv += xv[i] * xv[i];
    }
#pragma unroll
    for (int o = 16; o; o >>= 1) {
        sq += __shfl_xor_sync(0xffffffffu, sq, o);
        sk += __shfl_xor_sync(0xffffffffu, sk, o);
        sv += __shfl_xor_sync(0xffffffffu, sv, o);
    }
    __shared__ float s_q[8], s_k[8], s_v[8];
    if (lane == 0) { s_q[warp] = sq; s_k[warp] = sk; s_v[warp] = sv; }
    __syncthreads();
    float tq = 0.f, tk = 0.f, tv = 0.f;
#pragma unroll
    for (int w = 0; w < 8; w++) { tq += s_q[w]; tk += s_k[w]; tv += s_v[w]; }
    float rq = rsqrtf(tq * (1.0f / D_) + 1e-6f);
    float rk = rsqrtf(tk * (1.0f / D_) + 1e-6f);
    float rv = rsqrtf(tv * (1.0f / D_) + 1e-6f);

#pragma unroll
    for (int i = 0; i < 3; i++) {
        int j = tid + i * 256;
        int h = j >> 6, c = j & 63;
        int di = ((b * H_ + h) * P_ + p) * HD_ + c;
        g_qh[di] = xq[i] * rq * wq[j];
        g_vh[di] = xv[i] * rv * wv[j];
        g_khT[((size_t)(b * H_ + h) * HD_ + c) * P_ + p] = xk[i] * rk * wk[j];
    }
}

// ---------------------------------------------------------------------------
// Kernel 2: gather representative tokens (row-major + transposed).
// ---------------------------------------------------------------------------
__global__ __launch_bounds__(256) void k_rep(const int* __restrict__ idxs)
{
    int t = blockIdx.x * 256 + threadIdx.x;
    if (t >= H_ * NF * HD_) return;
    int c  = t & 63;
    int rj = (t >> 6) % NF;
    int h  = t / (NF * HD_);
    int nn = rj / PPR;
    int j  = rj % PPR;
    int sp = idxs[j];
    float val = g_vh[((nn * H_ + h) * P_ + sp) * HD_ + c];
    g_rep[t] = val;
    g_repT[(h * HD_ + c) * NF + rj] = val;
}

// ---------------------------------------------------------------------------
// Kernel 3: sim (coalesced repT, prefetched) + warp top-8 + sparse softmax
// + v_aligned. Block = 256 threads, PT=12 rows of one (b, h).
// __launch_bounds__(256, 4): cap regs at 64 so 4 blocks/SM fit (32 warps).
// ---------------------------------------------------------------------------
__global__ __launch_bounds__(256, 4) void k_align()
{
    int bid = blockIdx.x;
    int t  = bid % NT;
    int h  = (bid / NT) % H_;
    int b  = bid / (NT * H_);
    int p0 = t * PT;
    int tid = threadIdx.x;
    int lane = tid & 31, warp = tid >> 5;

    __shared__ float2 vp2[6][HD_];      // row-pair (2pr, 2pr+1) per column
    __shared__ float  sim[PT][NF];
    __shared__ int    kj[PT][64];
    __shared__ float  kw[PT][64];

    const float* vbase = g_vh + (size_t)(b * H_ + h) * P_ * HD_;

    // load row pairs
    for (int i = tid; i < 6 * HD_; i += 256) {
        int pr = i >> 6, c = i & 63;
        int r0 = p0 + 2 * pr;
        float a = (r0     < P_) ? vbase[(size_t)r0 * HD_ + c]       : 0.f;
        float d = (r0 + 1 < P_) ? vbase[(size_t)(r0 + 1) * HD_ + c] : 0.f;
        vp2[pr][c] = make_float2(a, d);
    }
    __syncthreads();

    const float* repT = g_repT + (size_t)h * HD_ * NF;
    int mlo = b * PPR;
    bool hasmask = (b < NREF);

    // Phase 1: 196 threads x 4 consecutive j, depth-2 LDG prefetch pipeline.
    if (tid < 196) {
        int jb = tid * 4;
        ull acc[4][6];   // [jj][pr]
#pragma unroll
        for (int jj = 0; jj < 4; jj++)
#pragma unroll
            for (int pr = 0; pr < 6; pr++) acc[jj][pr] = 0ull;

        const float* rb = repT + jb;
        float4 f0 = __ldg((const float4*)rb);
        float4 f1 = __ldg((const float4*)(rb + NF));

#pragma unroll 4
        for (int c = 0; c < HD_; c++) {
            float4 cur = f0;
            f0 = f1;
            if (c + 2 < HD_)
                f1 = __ldg((const float4*)(rb + (size_t)(c + 2) * NF));
            ull s0 = pack2(cur.x, cur.x), s1 = pack2(cur.y, cur.y);
            ull s2 = pack2(cur.z, cur.z), s3 = pack2(cur.w, cur.w);
#pragma unroll
            for (int pr = 0; pr < 6; pr++) {
                ull vpair = *(const ull*)&vp2[pr][c];   // broadcast LDS.64
                acc[0][pr] = fma2(s0, vpair, acc[0][pr]);
                acc[1][pr] = fma2(s1, vpair, acc[1][pr]);
                acc[2][pr] = fma2(s2, vpair, acc[2][pr]);
                acc[3][pr] = fma2(s3, vpair, acc[3][pr]);
            }
        }
#pragma unroll
        for (int jj = 0; jj < 4; jj++) {
            int j = jb + jj;
            bool selfm = hasmask && (j >= mlo) && (j < mlo + PPR);
#pragma unroll
            for (int pr = 0; pr < 6; pr++) {
                float x, y;
                unpack2(acc[jj][pr], x, y);
                sim[2 * pr + 0][j] = selfm ? NEGF : x;
                sim[2 * pr + 1][j] = selfm ? NEGF : y;
            }
        }
    }
    __syncthreads();

    const float* rep = g_rep + (size_t)h * NF * HD_;

    // Phases 2-3: warp-per-row (each warp handles rows warp, warp+8).
    for (int r = warp; r < PT; r += 8) {
        int row = p0 + r;
        if (row >= P_) break;

        // lane-local sorted top-8 over this lane's 25 entries
        float s0 = -CUDART_INF_F, s1 = s0, s2 = s0, s3 = s0,
              s4 = s0, s5 = s0, s6 = s0, s7 = s0;
#pragma unroll
        for (int tt = 0; tt < 25; tt++) {
            int j = tt * 32 + lane;
            float v = (j < NF) ? sim[r][j] : -CUDART_INF_F;
            float m;
            m = fmaxf(s0, v); v = fminf(s0, v); s0 = m;
            m = fmaxf(s1, v); v = fminf(s1, v); s1 = m;
            m = fmaxf(s2, v); v = fminf(s2, v); s2 = m;
            m = fmaxf(s3, v); v = fminf(s3, v); s3 = m;
            m = fmaxf(s4, v); v = fminf(s4, v); s4 = m;
            m = fmaxf(s5, v); v = fminf(s5, v); s5 = m;
            m = fmaxf(s6, v); v = fminf(s6, v); s6 = m;
            m = fmaxf(s7, v); v = fminf(s7, v); s7 = m;
        }
        // merge across lanes: 8 rounds of warp-max with multiplicity
        float mx = 0.f, thr = 0.f;
#pragma unroll
        for (int it = 0; it < 8; it++) {
            float m = s0;
#pragma unroll
            for (int o = 16; o; o >>= 1)
                m = fmaxf(m, __shfl_xor_sync(0xffffffffu, m, o));
            if (it == 0) mx  = m;
            if (it == 7) thr = m;
            unsigned msk = __ballot_sync(0xffffffffu, s0 == m);
            if (lane == (__ffs(msk) - 1)) {     // consume one instance
                s0 = s1; s1 = s2; s2 = s3; s3 = s4;
                s4 = s5; s5 = s6; s6 = s7; s7 = -CUDART_INF_F;
            }
        }

        // fused pass: denominator + compaction (weights stored UNnormalized)
        float ps = 0.f;
        int base = 0;
#pragma unroll
        for (int tt = 0; tt < 25; tt++) {
            int j = tt * 32 + lane;
            bool keep = false;
            float e = 0.f;
            if (j < NF) {
                float v = sim[r][j];
                if (v >= thr) { keep = true; e = expf(v - mx); ps += e; }
            }
            unsigned m2 = __ballot_sync(0xffffffffu, keep);
            if (keep) {
                int pos = base + __popc(m2 & ((1u << lane) - 1u));
                if (pos < 64) {
                    kj[r][pos] = j;
                    kw[r][pos] = e;
                }
            }
            base += __popc(m2);
        }
#pragma unroll
        for (int o = 16; o; o >>= 1)
            ps += __shfl_xor_sync(0xffffffffu, ps, o);
        float inv = 1.0f / ps;
        int nk = min(base, 64);
        __syncwarp();

        // gather: lane owns columns 2*lane, 2*lane+1; normalize at the end
        float2 vv = *(const float2*)(vbase + (size_t)row * HD_ + 2 * lane);
        float a0 = 0.f, a1 = 0.f;
        for (int kk = 0; kk < nk; kk++) {
            int jx = kj[r][kk];
            float w = kw[r][kk];
            float2 rv = *(const float2*)(rep + (size_t)jx * HD_ + 2 * lane);
            a0 += w * rv.x;
            a1 += w * rv.y;
        }
        a0 = vv.x + a0 * inv;
        a1 = vv.y + a1 * inv;
        *(float2*)(g_vsum + ((size_t)(b * H_ + h) * P_ + row) * HD_ + 2 * lane)
            = make_float2(a0, a1);
        __syncwarp();
    }
}

// ---------------------------------------------------------------------------
// Kernel 4: attention: softmax(q k^T * 0.125) @ vsum -> out (B,P,D).
// Block = PTA=16 rows of one (b, h); K read coalesced from g_khT.
// __launch_bounds__(256, 6): cap regs (~42) so 6 blocks/SM fit (occ ~72%).
// ---------------------------------------------------------------------------
__global__ __launch_bounds__(256, 6) void k_attn(float* __restrict__ out)
{
    int bid = blockIdx.x;
    int t  = bid % NTA;
    int h  = (bid / NTA) % H_;
    int b  = bid / (NTA * H_);
    int p0 = t * PTA;
    int tid = threadIdx.x;
    int lane = tid & 31, warp = tid >> 5;

    __shared__ float2 qp2[8][HD_];                   // q row pairs
    __shared__ __align__(16) float2 probp[8][198];   // prob row pairs (padded)
    __shared__ float  s_inv[PTA];
    __shared__ float  part[4][PTA][HD_];

    const float* qbase = g_qh + (size_t)(b * H_ + h) * P_ * HD_;
    for (int i = tid; i < 8 * HD_; i += 256) {
        int pr = i >> 6, c = i & 63;
        int r0 = p0 + 2 * pr;
        float a = (r0     < P_) ? qbase[(size_t)r0 * HD_ + c]       : 0.f;
        float d = (r0 + 1 < P_) ? qbase[(size_t)(r0 + 1) * HD_ + c] : 0.f;
        qp2[pr][c] = make_float2(a, d);
    }
    __syncthreads();

    // Phase A: logits; thread j = tid (<197), coalesced LDG.32 from khT.
    // K splat amortized over 8 row-pairs.
    if (tid < P_) {
        int j = tid;
        const float* khT = g_khT + (size_t)(b * H_ + h) * HD_ * P_;
        ull a[8] = {0ull, 0ull, 0ull, 0ull, 0ull, 0ull, 0ull, 0ull};
#pragma unroll 4
        for (int c = 0; c < HD_; c++) {
            float kv = __ldg(khT + (size_t)c * P_ + j);
            ull s = pack2(kv, kv);
#pragma unroll
            for (int pr = 0; pr < 8; pr++) {
                ull qpair = *(const ull*)&qp2[pr][c];
                a[pr] = fma2(s, qpair, a[pr]);
            }
        }
#pragma unroll
        for (int pr = 0; pr < 8; pr++) {
            float x, y;
            unpack2(a[pr], x, y);
            probp[pr][j] = make_float2(x * 0.125f, y * 0.125f);
        }
    }
    __syncthreads();

    // Phase B: warp-per-row softmax; each warp does rows warp, warp+8.
    for (int r = warp; r < PTA; r += 8) {
        if (p0 + r >= P_) break;
        int pr = r >> 1, comp = r & 1;
        float vals[7];
        float vmax = -CUDART_INF_F;
#pragma unroll
        for (int tt = 0; tt < 7; tt++) {
            int j = tt * 32 + lane;
            float x = -CUDART_INF_F;
            if (j < P_) x = ((const float*)&probp[pr][j])[comp];
            vals[tt] = x;
            vmax = fmaxf(vmax, x);
        }
#pragma unroll
        for (int o = 16; o; o >>= 1)
            vmax = fmaxf(vmax, __shfl_xor_sync(0xffffffffu, vmax, o));
        float ps = 0.f;
#pragma unroll
        for (int tt = 0; tt < 7; tt++) {
            int j = tt * 32 + lane;
            if (j < P_) {
                float e = expf(vals[tt] - vmax);
                ps += e;
                ((float*)&probp[pr][j])[comp] = e;
            }
        }
#pragma unroll
        for (int o = 16; o; o >>= 1)
            ps += __shfl_xor_sync(0xffffffffu, ps, o);
        if (lane == 0) s_inv[r] = 1.0f / ps;
        __syncwarp();
    }
    __syncthreads();

    // Phase C: AV with contiguous j-range per group; probp read as LDS.128.
    {
        int g = tid >> 6, c = tid & 63;
        int jlo = g * 50;
        int jhi = min(jlo + 50, P_);
        ull acc2[8] = {0ull, 0ull, 0ull, 0ull, 0ull, 0ull, 0ull, 0ull};
        const float* vb = g_vsum + (size_t)(b * H_ + h) * P_ * HD_;
        int j = jlo;
        for (; j + 1 < jhi; j += 2) {
            float va  = __ldg(vb + (size_t)j * HD_ + c);
            float vbv = __ldg(vb + (size_t)(j + 1) * HD_ + c);
            ull v2a = pack2(va, va);
            ull v2b = pack2(vbv, vbv);
#pragma unroll
            for (int pr = 0; pr < 8; pr++) {
                float4 wp = *(const float4*)&probp[pr][j];   // (j, j+1) pairs
                acc2[pr] = fma2(lo2(wp), v2a, acc2[pr]);
                acc2[pr] = fma2(hi2(wp), v2b, acc2[pr]);
            }
        }
        if (j < jhi) {
            float va = __ldg(vb + (size_t)j * HD_ + c);
            ull v2a = pack2(va, va);
#pragma unroll
            for (int pr = 0; pr < 8; pr++) {
                ull w = *(const ull*)&probp[pr][j];
                acc2[pr] = fma2(w, v2a, acc2[pr]);
            }
        }
#pragma unroll
        for (int pr = 0; pr < 8; pr++) {
            float x, y;
            unpack2(acc2[pr], x, y);
            part[g][2 * pr + 0][c] = x;
            part[g][2 * pr + 1][c] = y;
        }
    }
    __syncthreads();

    // epilogue: normalize + write
    for (int rr = tid >> 6; rr < PTA; rr += 4) {
        int cc = tid & 63;
        if (p0 + rr < P_) {
            float s = part[0][rr][cc] + part[1][rr][cc]
                    + part[2][rr][cc] + part[3][rr][cc];
            out[((size_t)b * P_ + p0 + rr) * D_ + h * HD_ + cc] = s * s_inv[rr];
        }
    }
}

// ---------------------------------------------------------------------------
extern "C" void kernel_launch(void* const* d_in, const int* in_sizes, int n_in,
                              void* d_out, int out_size)
{
    const float* q   = (const float*)d_in[0];
    const float* k   = (const float*)d_in[1];
    const float* v   = (const float*)d_in[2];
    const float* wq  = (const float*)d_in[3];
    const float* wk  = (const float*)d_in[4];
    const float* wv  = (const float*)d_in[5];
    const int* idxs  = (const int*)d_in[6];
    float* out = (float*)d_out;

    k_rms<<<B_ * P_, 256>>>(q, k, v, wq, wk, wv);
    k_rep<<<(H_ * NF * HD_ + 255) / 256, 256>>>(idxs);
    k_align<<<B_ * H_ * NT, 256>>>();
    k_attn<<<B_ * H_ * NTA, 256>>>(out);
}

// round 14
// speedup vs baseline: 1.4036x; 1.4036x over previous
#include <cuda_runtime.h>
#include <math_constants.h>

typedef unsigned long long ull;

namespace {
constexpr int B_   = 32;
constexpr int P_   = 197;
constexpr int D_   = 768;
constexpr int H_   = 12;
constexpr int HD_  = 64;
constexpr int PPR  = 49;    // rep tokens per reference sample
constexpr int NREF = 16;    // int(B * 0.5)
constexpr int NF   = 784;   // NREF * PPR
constexpr int PT   = 8;     // rows per block in k_align (acc tile 32 regs)
constexpr int NT   = (P_ + PT - 1) / PT;   // 25
constexpr int PTA  = 16;    // rows per block in k_attn
constexpr int NTA  = (P_ + PTA - 1) / PTA; // 13
constexpr float NEGF = -1e30f;
}

// scratch (device globals; no allocation allowed)
__device__ float g_qh  [B_ * H_ * P_ * HD_];
__device__ float g_khT [B_ * H_ * HD_ * P_];   // [b][h][c][p]
__device__ float g_vh  [B_ * H_ * P_ * HD_];
__device__ float g_vsum[B_ * H_ * P_ * HD_];
__device__ float g_rep [H_ * NF * HD_];        // [h][j][c]
__device__ float g_repT[H_ * HD_ * NF];        // [h][c][j]

// ---- packed f32x2 helpers (sm_103a) --------------------------------------
__device__ __forceinline__ ull pack2(float x, float y) {
    ull r; asm("mov.b64 %0, {%1, %2};" : "=l"(r) : "f"(x), "f"(y)); return r;
}
__device__ __forceinline__ ull fma2(ull a, ull b, ull c) {
    ull d; asm("fma.rn.f32x2 %0, %1, %2, %3;" : "=l"(d) : "l"(a), "l"(b), "l"(c));
    return d;
}
__device__ __forceinline__ void unpack2(ull p, float& x, float& y) {
    asm("mov.b64 {%0, %1}, %2;" : "=f"(x), "=f"(y) : "l"(p));
}
__device__ __forceinline__ ull lo2(const float4& v) {
    ull r; asm("mov.b64 %0, {%1, %2};" : "=l"(r) : "f"(v.x), "f"(v.y)); return r;
}
__device__ __forceinline__ ull hi2(const float4& v) {
    ull r; asm("mov.b64 %0, {%1, %2};" : "=l"(r) : "f"(v.z), "f"(v.w)); return r;
}

// ---------------------------------------------------------------------------
// Kernel 1: RMSNorm (over D=768) + head split. K written transposed.
// ---------------------------------------------------------------------------
__global__ __launch_bounds__(256) void k_rms(
    const float* __restrict__ q, const float* __restrict__ k,
    const float* __restrict__ v, const float* __restrict__ wq,
    const float* __restrict__ wk, const float* __restrict__ wv)
{
    int bp = blockIdx.x;
    int b = bp / P_;
    int p = bp % P_;
    int tid = threadIdx.x;
    int lane = tid & 31, warp = tid >> 5;
    size_t off = (size_t)bp * D_;

    float xq[3], xk[3], xv[3];
    float sq = 0.f, sk = 0.f, sv = 0.f;
#pragma unroll
    for (int i = 0; i < 3; i++) {
        int j = tid + i * 256;
        xq[i] = q[off + j]; sq += xq[i] * xq[i];
        xk[i] = k[off + j]; sk += xk[i] * xk[i];
        xv[i] = v[off + j]; sv += xv[i] * xv[i];
    }
#pragma unroll
    for (int o = 16; o; o >>= 1) {
        sq += __shfl_xor_sync(0xffffffffu, sq, o);
        sk += __shfl_xor_sync(0xffffffffu, sk, o);
        sv += __shfl_xor_sync(0xffffffffu, sv, o);
    }
    __shared__ float s_q[8], s_k[8], s_v[8];
    if (lane == 0) { s_q[warp] = sq; s_k[warp] = sk; s_v[warp] = sv; }
    __syncthreads();
    float tq = 0.f, tk = 0.f, tv = 0.f;
#pragma unroll
    for (int w = 0; w < 8; w++) { tq += s_q[w]; tk += s_k[w]; tv += s_v[w]; }
    float rq = rsqrtf(tq * (1.0f / D_) + 1e-6f);
    float rk = rsqrtf(tk * (1.0f / D_) + 1e-6f);
    float rv = rsqrtf(tv * (1.0f / D_) + 1e-6f);

#pragma unroll
    for (int i = 0; i < 3; i++) {
        int j = tid + i * 256;
        int h = j >> 6, c = j & 63;
        int di = ((b * H_ + h) * P_ + p) * HD_ + c;
        g_qh[di] = xq[i] * rq * wq[j];
        g_vh[di] = xv[i] * rv * wv[j];
        g_khT[((size_t)(b * H_ + h) * HD_ + c) * P_ + p] = xk[i] * rk * wk[j];
    }
}

// ---------------------------------------------------------------------------
// Kernel 2: gather representative tokens (row-major + transposed).
// ---------------------------------------------------------------------------
__global__ __launch_bounds__(256) void k_rep(const int* __restrict__ idxs)
{
    int t = blockIdx.x * 256 + threadIdx.x;
    if (t >= H_ * NF * HD_) return;
    int c  = t & 63;
    int rj = (t >> 6) % NF;
    int h  = t / (NF * HD_);
    int nn = rj / PPR;
    int j  = rj % PPR;
    int sp = idxs[j];
    float val = g_vh[((nn * H_ + h) * P_ + sp) * HD_ + c];
    g_rep[t] = val;
    g_repT[(h * HD_ + c) * NF + rj] = val;
}

// ---------------------------------------------------------------------------
// Kernel 3: sim (coalesced repT, prefetched) + warp top-8 + sparse softmax
// + v_aligned. Block = 256 threads, PT=8 rows of one (b, h).
// acc[4][4] = 32 regs -> ~55 total -> 4 blocks/SM naturally (no coercion).
// ---------------------------------------------------------------------------
__global__ __launch_bounds__(256) void k_align()
{
    int bid = blockIdx.x;
    int t  = bid % NT;
    int h  = (bid / NT) % H_;
    int b  = bid / (NT * H_);
    int p0 = t * PT;
    int tid = threadIdx.x;
    int lane = tid & 31, warp = tid >> 5;

    __shared__ float2 vp2[4][HD_];      // row-pair (2pr, 2pr+1) per column
    __shared__ float  sim[PT][NF];
    __shared__ int    kj[PT][64];
    __shared__ float  kw[PT][64];

    const float* vbase = g_vh + (size_t)(b * H_ + h) * P_ * HD_;

    // load row pairs
    for (int i = tid; i < 4 * HD_; i += 256) {
        int pr = i >> 6, c = i & 63;
        int r0 = p0 + 2 * pr;
        float a = (r0     < P_) ? vbase[(size_t)r0 * HD_ + c]       : 0.f;
        float d = (r0 + 1 < P_) ? vbase[(size_t)(r0 + 1) * HD_ + c] : 0.f;
        vp2[pr][c] = make_float2(a, d);
    }
    __syncthreads();

    const float* repT = g_repT + (size_t)h * HD_ * NF;
    int mlo = b * PPR;
    bool hasmask = (b < NREF);

    // Phase 1: 196 threads x 4 consecutive j, depth-2 LDG prefetch pipeline.
    if (tid < 196) {
        int jb = tid * 4;
        ull acc[4][4];   // [jj][pr]
#pragma unroll
        for (int jj = 0; jj < 4; jj++)
#pragma unroll
            for (int pr = 0; pr < 4; pr++) acc[jj][pr] = 0ull;

        const float* rb = repT + jb;
        float4 f0 = __ldg((const float4*)rb);
        float4 f1 = __ldg((const float4*)(rb + NF));

#pragma unroll 4
        for (int c = 0; c < HD_; c++) {
            float4 cur = f0;
            f0 = f1;
            if (c + 2 < HD_)
                f1 = __ldg((const float4*)(rb + (size_t)(c + 2) * NF));
            ull s0 = pack2(cur.x, cur.x), s1 = pack2(cur.y, cur.y);
            ull s2 = pack2(cur.z, cur.z), s3 = pack2(cur.w, cur.w);
#pragma unroll
            for (int pr = 0; pr < 4; pr++) {
                ull vpair = *(const ull*)&vp2[pr][c];   // broadcast LDS.64
                acc[0][pr] = fma2(s0, vpair, acc[0][pr]);
                acc[1][pr] = fma2(s1, vpair, acc[1][pr]);
                acc[2][pr] = fma2(s2, vpair, acc[2][pr]);
                acc[3][pr] = fma2(s3, vpair, acc[3][pr]);
            }
        }
#pragma unroll
        for (int jj = 0; jj < 4; jj++) {
            int j = jb + jj;
            bool selfm = hasmask && (j >= mlo) && (j < mlo + PPR);
#pragma unroll
            for (int pr = 0; pr < 4; pr++) {
                float x, y;
                unpack2(acc[jj][pr], x, y);
                sim[2 * pr + 0][j] = selfm ? NEGF : x;
                sim[2 * pr + 1][j] = selfm ? NEGF : y;
            }
        }
    }
    __syncthreads();

    const float* rep = g_rep + (size_t)h * NF * HD_;

    // Phases 2-3: exactly one warp per row.
    int r = warp;
    int row = p0 + r;
    if (row < P_) {
        // lane-local sorted top-8 over this lane's 25 entries
        float s0 = -CUDART_INF_F, s1 = s0, s2 = s0, s3 = s0,
              s4 = s0, s5 = s0, s6 = s0, s7 = s0;
#pragma unroll
        for (int tt = 0; tt < 25; tt++) {
            int j = tt * 32 + lane;
            float v = (j < NF) ? sim[r][j] : -CUDART_INF_F;
            float m;
            m = fmaxf(s0, v); v = fminf(s0, v); s0 = m;
            m = fmaxf(s1, v); v = fminf(s1, v); s1 = m;
            m = fmaxf(s2, v); v = fminf(s2, v); s2 = m;
            m = fmaxf(s3, v); v = fminf(s3, v); s3 = m;
            m = fmaxf(s4, v); v = fminf(s4, v); s4 = m;
            m = fmaxf(s5, v); v = fminf(s5, v); s5 = m;
            m = fmaxf(s6, v); v = fminf(s6, v); s6 = m;
            m = fmaxf(s7, v); v = fminf(s7, v); s7 = m;
        }
        // merge across lanes: 8 rounds of warp-max with multiplicity
        float mx = 0.f, thr = 0.f;
#pragma unroll
        for (int it = 0; it < 8; it++) {
            float m = s0;
#pragma unroll
            for (int o = 16; o; o >>= 1)
                m = fmaxf(m, __shfl_xor_sync(0xffffffffu, m, o));
            if (it == 0) mx  = m;
            if (it == 7) thr = m;
            unsigned msk = __ballot_sync(0xffffffffu, s0 == m);
            if (lane == (__ffs(msk) - 1)) {     // consume one instance
                s0 = s1; s1 = s2; s2 = s3; s3 = s4;
                s4 = s5; s5 = s6; s6 = s7; s7 = -CUDART_INF_F;
            }
        }

        // fused pass: denominator + compaction (weights stored UNnormalized)
        float ps = 0.f;
        int base = 0;
#pragma unroll
        for (int tt = 0; tt < 25; tt++) {
            int j = tt * 32 + lane;
            bool keep = false;
            float e = 0.f;
            if (j < NF) {
                float v = sim[r][j];
                if (v >= thr) { keep = true; e = expf(v - mx); ps += e; }
            }
            unsigned m2 = __ballot_sync(0xffffffffu, keep);
            if (keep) {
                int pos = base + __popc(m2 & ((1u << lane) - 1u));
                if (pos < 64) {
                    kj[r][pos] = j;
                    kw[r][pos] = e;
                }
            }
            base += __popc(m2);
        }
#pragma unroll
        for (int o = 16; o; o >>= 1)
            ps += __shfl_xor_sync(0xffffffffu, ps, o);
        float inv = 1.0f / ps;
        int nk = min(base, 64);
        __syncwarp();

        // gather: lane owns columns 2*lane, 2*lane+1; normalize at the end
        float2 vv = *(const float2*)(vbase + (size_t)row * HD_ + 2 * lane);
        float a0 = 0.f, a1 = 0.f;
        for (int kk = 0; kk < nk; kk++) {
            int jx = kj[r][kk];
            float w = kw[r][kk];
            float2 rv = *(const float2*)(rep + (size_t)jx * HD_ + 2 * lane);
            a0 += w * rv.x;
            a1 += w * rv.y;
        }
        a0 = vv.x + a0 * inv;
        a1 = vv.y + a1 * inv;
        *(float2*)(g_vsum + ((size_t)(b * H_ + h) * P_ + row) * HD_ + 2 * lane)
            = make_float2(a0, a1);
    }
}

// ---------------------------------------------------------------------------
// Kernel 4: attention: softmax(q k^T * 0.125) @ vsum -> out (B,P,D).
// Block = PTA=16 rows of one (b, h); K read coalesced from g_khT.
// __launch_bounds__(256, 6): regs ~40, 6 blocks/SM (occ ~72%).
// ---------------------------------------------------------------------------
__global__ __launch_bounds__(256, 6) void k_attn(float* __restrict__ out)
{
    int bid = blockIdx.x;
    int t  = bid % NTA;
    int h  = (bid / NTA) % H_;
    int b  = bid / (NTA * H_);
    int p0 = t * PTA;
    int tid = threadIdx.x;
    int lane = tid & 31, warp = tid >> 5;

    __shared__ float2 qp2[8][HD_];                   // q row pairs
    __shared__ __align__(16) float2 probp[8][198];   // prob row pairs (padded)
    __shared__ float  s_inv[PTA];
    __shared__ float  part[4][PTA][HD_];

    const float* qbase = g_qh + (size_t)(b * H_ + h) * P_ * HD_;
    for (int i = tid; i < 8 * HD_; i += 256) {
        int pr = i >> 6, c = i & 63;
        int r0 = p0 + 2 * pr;
        float a = (r0     < P_) ? qbase[(size_t)r0 * HD_ + c]       : 0.f;
        float d = (r0 + 1 < P_) ? qbase[(size_t)(r0 + 1) * HD_ + c] : 0.f;
        qp2[pr][c] = make_float2(a, d);
    }
    __syncthreads();

    // Phase A: logits; thread j = tid (<197), coalesced LDG.32 from khT.
    // K splat amortized over 8 row-pairs.
    if (tid < P_) {
        int j = tid;
        const float* khT = g_khT + (size_t)(b * H_ + h) * HD_ * P_;
        ull a[8] = {0ull, 0ull, 0ull, 0ull, 0ull, 0ull, 0ull, 0ull};
#pragma unroll 4
        for (int c = 0; c < HD_; c++) {
            float kv = __ldg(khT + (size_t)c * P_ + j);
            ull s = pack2(kv, kv);
#pragma unroll
            for (int pr = 0; pr < 8; pr++) {
                ull qpair = *(const ull*)&qp2[pr][c];
                a[pr] = fma2(s, qpair, a[pr]);
            }
        }
#pragma unroll
        for (int pr = 0; pr < 8; pr++) {
            float x, y;
            unpack2(a[pr], x, y);
            probp[pr][j] = make_float2(x * 0.125f, y * 0.125f);
        }
    }
    __syncthreads();

    // Phase B: warp-per-row softmax; each warp does rows warp, warp+8.
    for (int r = warp; r < PTA; r += 8) {
        if (p0 + r >= P_) break;
        int pr = r >> 1, comp = r & 1;
        float vals[7];
        float vmax = -CUDART_INF_F;
#pragma unroll
        for (int tt = 0; tt < 7; tt++) {
            int j = tt * 32 + lane;
            float x = -CUDART_INF_F;
            if (j < P_) x = ((const float*)&probp[pr][j])[comp];
            vals[tt] = x;
            vmax = fmaxf(vmax, x);
        }
#pragma unroll
        for (int o = 16; o; o >>= 1)
            vmax = fmaxf(vmax, __shfl_xor_sync(0xffffffffu, vmax, o));
        float ps = 0.f;
#pragma unroll
        for (int tt = 0; tt < 7; tt++) {
            int j = tt * 32 + lane;
            if (j < P_) {
                float e = expf(vals[tt] - vmax);
                ps += e;
                ((float*)&probp[pr][j])[comp] = e;
            }
        }
#pragma unroll
        for (int o = 16; o; o >>= 1)
            ps += __shfl_xor_sync(0xffffffffu, ps, o);
        if (lane == 0) s_inv[r] = 1.0f / ps;
        __syncwarp();
    }
    __syncthreads();

    // Phase C: AV with contiguous j-range per group; probp read as LDS.128.
    {
        int g = tid >> 6, c = tid & 63;
        int jlo = g * 50;
        int jhi = min(jlo + 50, P_);
        ull acc2[8] = {0ull, 0ull, 0ull, 0ull, 0ull, 0ull, 0ull, 0ull};
        const float* vb = g_vsum + (size_t)(b * H_ + h) * P_ * HD_;
        int j = jlo;
        for (; j + 1 < jhi; j += 2) {
            float va  = __ldg(vb + (size_t)j * HD_ + c);
            float vbv = __ldg(vb + (size_t)(j + 1) * HD_ + c);
            ull v2a = pack2(va, va);
            ull v2b = pack2(vbv, vbv);
#pragma unroll
            for (int pr = 0; pr < 8; pr++) {
                float4 wp = *(const float4*)&probp[pr][j];   // (j, j+1) pairs
                acc2[pr] = fma2(lo2(wp), v2a, acc2[pr]);
                acc2[pr] = fma2(hi2(wp), v2b, acc2[pr]);
            }
        }
        if (j < jhi) {
            float va = __ldg(vb + (size_t)j * HD_ + c);
            ull v2a = pack2(va, va);
#pragma unroll
            for (int pr = 0; pr < 8; pr++) {
                ull w = *(const ull*)&probp[pr][j];
                acc2[pr] = fma2(w, v2a, acc2[pr]);
            }
        }
#pragma unroll
        for (int pr = 0; pr < 8; pr++) {
            float x, y;
            unpack2(acc2[pr], x, y);
            part[g][2 * pr + 0][c] = x;
            part[g][2 * pr + 1][c] = y;
        }
    }
    __syncthreads();

    // epilogue: normalize + write
    for (int rr = tid >> 6; rr < PTA; rr += 4) {
        int cc = tid & 63;
        if (p0 + rr < P_) {
            float s = part[0][rr][cc] + part[1][rr][cc]
                    + part[2][rr][cc] + part[3][rr][cc];
            out[((size_t)b * P_ + p0 + rr) * D_ + h * HD_ + cc] = s * s_inv[rr];
        }
    }
}

// ---------------------------------------------------------------------------
extern "C" void kernel_launch(void* const* d_in, const int* in_sizes, int n_in,
                              void* d_out, int out_size)
{
    const float* q   = (const float*)d_in[0];
    const float* k   = (const float*)d_in[1];
    const float* v   = (const float*)d_in[2];
    const float* wq  = (const float*)d_in[3];
    const float* wk  = (const float*)d_in[4];
    const float* wv  = (const float*)d_in[5];
    const int* idxs  = (const int*)d_in[6];
    float* out = (float*)d_out;

    k_rms<<<B_ * P_, 256>>>(q, k, v, wq, wk, wv);
    k_rep<<<(H_ * NF * HD_ + 255) / 256, 256>>>(idxs);
    k_align<<<B_ * H_ * NT, 256>>>();
    k_attn<<<B_ * H_ * NTA, 256>>>(out);
}

// round 15
// speedup vs baseline: 1.4551x; 1.0367x over previous
#include <cuda_runtime.h>
#include <math_constants.h>

typedef unsigned long long ull;

namespace {
constexpr int B_   = 32;
constexpr int P_   = 197;
constexpr int D_   = 768;
constexpr int H_   = 12;
constexpr int HD_  = 64;
constexpr int PPR  = 49;    // rep tokens per reference sample
constexpr int NREF = 16;    // int(B * 0.5)
constexpr int NF   = 784;   // NREF * PPR
constexpr int PT   = 8;     // rows per block in k_align
constexpr int NT   = (P_ + PT - 1) / PT;   // 25
constexpr int PTA  = 16;    // rows per block in k_attn
constexpr int NTA  = (P_ + PTA - 1) / PTA; // 13
constexpr float NEGF = -1e30f;
}

// scratch (device globals; no allocation allowed)
__device__ float g_qh  [B_ * H_ * P_ * HD_];
__device__ float g_khT [B_ * H_ * HD_ * P_];   // [b][h][c][p]
__device__ float g_vh  [B_ * H_ * P_ * HD_];
__device__ float g_vsum[B_ * H_ * P_ * HD_];
__device__ float g_rep [H_ * NF * HD_];        // [h][j][c]
__device__ float g_repT[H_ * HD_ * NF];        // [h][c][j]

// ---- packed f32x2 helpers (sm_103a) --------------------------------------
__device__ __forceinline__ ull pack2(float x, float y) {
    ull r; asm("mov.b64 %0, {%1, %2};" : "=l"(r) : "f"(x), "f"(y)); return r;
}
__device__ __forceinline__ ull fma2(ull a, ull b, ull c) {
    ull d; asm("fma.rn.f32x2 %0, %1, %2, %3;" : "=l"(d) : "l"(a), "l"(b), "l"(c));
    return d;
}
__device__ __forceinline__ void unpack2(ull p, float& x, float& y) {
    asm("mov.b64 {%0, %1}, %2;" : "=f"(x), "=f"(y) : "l"(p));
}
__device__ __forceinline__ ull lo2(const float4& v) {   // (x,y) pair — free
    ull r; asm("mov.b64 %0, {%1, %2};" : "=l"(r) : "f"(v.x), "f"(v.y)); return r;
}
__device__ __forceinline__ ull hi2(const float4& v) {   // (z,w) pair — free
    ull r; asm("mov.b64 %0, {%1, %2};" : "=l"(r) : "f"(v.z), "f"(v.w)); return r;
}

// ---------------------------------------------------------------------------
// Kernel 1: RMSNorm (over D=768) + head split. K written transposed.
// ---------------------------------------------------------------------------
__global__ __launch_bounds__(256) void k_rms(
    const float* __restrict__ q, const float* __restrict__ k,
    const float* __restrict__ v, const float* __restrict__ wq,
    const float* __restrict__ wk, const float* __restrict__ wv)
{
    int bp = blockIdx.x;
    int b = bp / P_;
    int p = bp % P_;
    int tid = threadIdx.x;
    int lane = tid & 31, warp = tid >> 5;
    size_t off = (size_t)bp * D_;

    float xq[3], xk[3], xv[3];
    float sq = 0.f, sk = 0.f, sv = 0.f;
#pragma unroll
    for (int i = 0; i < 3; i++) {
        int j = tid + i * 256;
        xq[i] = q[off + j]; sq += xq[i] * xq[i];
        xk[i] = k[off + j]; sk += xk[i] * xk[i];
        xv[i] = v[off + j]; sv += xv[i] * xv[i];
    }
#pragma unroll
    for (int o = 16; o; o >>= 1) {
        sq += __shfl_xor_sync(0xffffffffu, sq, o);
        sk += __shfl_xor_sync(0xffffffffu, sk, o);
        sv += __shfl_xor_sync(0xffffffffu, sv, o);
    }
    __shared__ float s_q[8], s_k[8], s_v[8];
    if (lane == 0) { s_q[warp] = sq; s_k[warp] = sk; s_v[warp] = sv; }
    __syncthreads();
    float tq = 0.f, tk = 0.f, tv = 0.f;
#pragma unroll
    for (int w = 0; w < 8; w++) { tq += s_q[w]; tk += s_k[w]; tv += s_v[w]; }
    float rq = rsqrtf(tq * (1.0f / D_) + 1e-6f);
    float rk = rsqrtf(tk * (1.0f / D_) + 1e-6f);
    float rv = rsqrtf(tv * (1.0f / D_) + 1e-6f);

#pragma unroll
    for (int i = 0; i < 3; i++) {
        int j = tid + i * 256;
        int h = j >> 6, c = j & 63;
        int di = ((b * H_ + h) * P_ + p) * HD_ + c;
        g_qh[di] = xq[i] * rq * wq[j];
        g_vh[di] = xv[i] * rv * wv[j];
        g_khT[((size_t)(b * H_ + h) * HD_ + c) * P_ + p] = xk[i] * rk * wk[j];
    }
}

// ---------------------------------------------------------------------------
// Kernel 2: gather representative tokens (row-major + transposed).
// ---------------------------------------------------------------------------
__global__ __launch_bounds__(256) void k_rep(const int* __restrict__ idxs)
{
    int t = blockIdx.x * 256 + threadIdx.x;
    if (t >= H_ * NF * HD_) return;
    int c  = t & 63;
    int rj = (t >> 6) % NF;
    int h  = t / (NF * HD_);
    int nn = rj / PPR;
    int j  = rj % PPR;
    int sp = idxs[j];
    float val = g_vh[((nn * H_ + h) * P_ + sp) * HD_ + c];
    g_rep[t] = val;
    g_repT[(h * HD_ + c) * NF + rj] = val;
}

// ---------------------------------------------------------------------------
// Kernel 3: sim (coalesced repT, prefetched, 4-row float4 v-tile) +
// warp top-8 + sparse softmax + v_aligned. PT=8 rows of one (b, h).
// vp4[g4][c] = rows (p0+4g4 .. p0+4g4+3) at column c; lo2->pair 2g4, hi2->2g4+1.
// ---------------------------------------------------------------------------
__global__ __launch_bounds__(256) void k_align()
{
    int bid = blockIdx.x;
    int t  = bid % NT;
    int h  = (bid / NT) % H_;
    int b  = bid / (NT * H_);
    int p0 = t * PT;
    int tid = threadIdx.x;
    int lane = tid & 31, warp = tid >> 5;

    __shared__ __align__(16) float4 vp4[2][HD_];   // 4-row groups per column
    __shared__ float  sim[PT][NF];
    __shared__ int    kj[PT][64];
    __shared__ float  kw[PT][64];

    const float* vbase = g_vh + (size_t)(b * H_ + h) * P_ * HD_;

    // load 4-row groups per column
    for (int i = tid; i < 2 * HD_; i += 256) {
        int g4 = i >> 6, c = i & 63;
        int r0 = p0 + 4 * g4;
        float x = (r0     < P_) ? vbase[(size_t)r0 * HD_ + c]       : 0.f;
        float y = (r0 + 1 < P_) ? vbase[(size_t)(r0 + 1) * HD_ + c] : 0.f;
        float z = (r0 + 2 < P_) ? vbase[(size_t)(r0 + 2) * HD_ + c] : 0.f;
        float w = (r0 + 3 < P_) ? vbase[(size_t)(r0 + 3) * HD_ + c] : 0.f;
        vp4[g4][c] = make_float4(x, y, z, w);
    }
    __syncthreads();

    const float* repT = g_repT + (size_t)h * HD_ * NF;
    int mlo = b * PPR;
    bool hasmask = (b < NREF);

    // Phase 1: 196 threads x 4 consecutive j, depth-2 LDG prefetch pipeline.
    // Per c: 2 LDS.128 (broadcast) + 16 FFMA2 + amortized LDG.
    if (tid < 196) {
        int jb = tid * 4;
        ull acc[4][4];   // [jj][pr], pr = row pair (2pr, 2pr+1)
#pragma unroll
        for (int jj = 0; jj < 4; jj++)
#pragma unroll
            for (int pr = 0; pr < 4; pr++) acc[jj][pr] = 0ull;

        const float* rb = repT + jb;
        float4 f0 = __ldg((const float4*)rb);
        float4 f1 = __ldg((const float4*)(rb + NF));

#pragma unroll 4
        for (int c = 0; c < HD_; c++) {
            float4 cur = f0;
            f0 = f1;
            if (c + 2 < HD_)
                f1 = __ldg((const float4*)(rb + (size_t)(c + 2) * NF));
            ull s0 = pack2(cur.x, cur.x), s1 = pack2(cur.y, cur.y);
            ull s2 = pack2(cur.z, cur.z), s3 = pack2(cur.w, cur.w);
#pragma unroll
            for (int g4 = 0; g4 < 2; g4++) {
                float4 vv = vp4[g4][c];       // LDS.128 broadcast
                ull vlo = lo2(vv), vhi = hi2(vv);
                acc[0][2 * g4 + 0] = fma2(s0, vlo, acc[0][2 * g4 + 0]);
                acc[0][2 * g4 + 1] = fma2(s0, vhi, acc[0][2 * g4 + 1]);
                acc[1][2 * g4 + 0] = fma2(s1, vlo, acc[1][2 * g4 + 0]);
                acc[1][2 * g4 + 1] = fma2(s1, vhi, acc[1][2 * g4 + 1]);
                acc[2][2 * g4 + 0] = fma2(s2, vlo, acc[2][2 * g4 + 0]);
                acc[2][2 * g4 + 1] = fma2(s2, vhi, acc[2][2 * g4 + 1]);
                acc[3][2 * g4 + 0] = fma2(s3, vlo, acc[3][2 * g4 + 0]);
                acc[3][2 * g4 + 1] = fma2(s3, vhi, acc[3][2 * g4 + 1]);
            }
        }
#pragma unroll
        for (int jj = 0; jj < 4; jj++) {
            int j = jb + jj;
            bool selfm = hasmask && (j >= mlo) && (j < mlo + PPR);
#pragma unroll
            for (int pr = 0; pr < 4; pr++) {
                float x, y;
                unpack2(acc[jj][pr], x, y);
                sim[2 * pr + 0][j] = selfm ? NEGF : x;
                sim[2 * pr + 1][j] = selfm ? NEGF : y;
            }
        }
    }
    __syncthreads();

    const float* rep = g_rep + (size_t)h * NF * HD_;

    // Phases 2-3: exactly one warp per row.
    int r = warp;
    int row = p0 + r;
    if (row < P_) {
        // lane-local sorted top-8 over this lane's 25 entries
        float s0 = -CUDART_INF_F, s1 = s0, s2 = s0, s3 = s0,
              s4 = s0, s5 = s0, s6 = s0, s7 = s0;
#pragma unroll
        for (int tt = 0; tt < 25; tt++) {
            int j = tt * 32 + lane;
            float v = (j < NF) ? sim[r][j] : -CUDART_INF_F;
            float m;
            m = fmaxf(s0, v); v = fminf(s0, v); s0 = m;
            m = fmaxf(s1, v); v = fminf(s1, v); s1 = m;
            m = fmaxf(s2, v); v = fminf(s2, v); s2 = m;
            m = fmaxf(s3, v); v = fminf(s3, v); s3 = m;
            m = fmaxf(s4, v); v = fminf(s4, v); s4 = m;
            m = fmaxf(s5, v); v = fminf(s5, v); s5 = m;
            m = fmaxf(s6, v); v = fminf(s6, v); s6 = m;
            m = fmaxf(s7, v); v = fminf(s7, v); s7 = m;
        }
        // merge across lanes: 8 rounds of warp-max with multiplicity
        float mx = 0.f, thr = 0.f;
#pragma unroll
        for (int it = 0; it < 8; it++) {
            float m = s0;
#pragma unroll
            for (int o = 16; o; o >>= 1)
                m = fmaxf(m, __shfl_xor_sync(0xffffffffu, m, o));
            if (it == 0) mx  = m;
            if (it == 7) thr = m;
            unsigned msk = __ballot_sync(0xffffffffu, s0 == m);
            if (lane == (__ffs(msk) - 1)) {     // consume one instance
                s0 = s1; s1 = s2; s2 = s3; s3 = s4;
                s4 = s5; s5 = s6; s6 = s7; s7 = -CUDART_INF_F;
            }
        }

        // fused pass: denominator + compaction (weights stored UNnormalized)
        float ps = 0.f;
        int base = 0;
#pragma unroll
        for (int tt = 0; tt < 25; tt++) {
            int j = tt * 32 + lane;
            bool keep = false;
            float e = 0.f;
            if (j < NF) {
                float v = sim[r][j];
                if (v >= thr) { keep = true; e = expf(v - mx); ps += e; }
            }
            unsigned m2 = __ballot_sync(0xffffffffu, keep);
            if (keep) {
                int pos = base + __popc(m2 & ((1u << lane) - 1u));
                if (pos < 64) {
                    kj[r][pos] = j;
                    kw[r][pos] = e;
                }
            }
            base += __popc(m2);
        }
#pragma unroll
        for (int o = 16; o; o >>= 1)
            ps += __shfl_xor_sync(0xffffffffu, ps, o);
        float inv = 1.0f / ps;
        int nk = min(base, 64);
        __syncwarp();

        // gather: lane owns columns 2*lane, 2*lane+1; normalize at the end
        float2 vv = *(const float2*)(vbase + (size_t)row * HD_ + 2 * lane);
        float a0 = 0.f, a1 = 0.f;
        for (int kk = 0; kk < nk; kk++) {
            int jx = kj[r][kk];
            float w = kw[r][kk];
            float2 rv = *(const float2*)(rep + (size_t)jx * HD_ + 2 * lane);
            a0 += w * rv.x;
            a1 += w * rv.y;
        }
        a0 = vv.x + a0 * inv;
        a1 = vv.y + a1 * inv;
        *(float2*)(g_vsum + ((size_t)(b * H_ + h) * P_ + row) * HD_ + 2 * lane)
            = make_float2(a0, a1);
    }
}

// ---------------------------------------------------------------------------
// Kernel 4: attention: softmax(q k^T * 0.125) @ vsum -> out (B,P,D).
// PTA=16 rows of one (b, h); K coalesced; q tile as 4-row float4 groups.
// qp4[g4][c] = rows (p0+4g4 .. p0+4g4+3) at column c.
// __launch_bounds__(256, 6): regs ~40, 6 blocks/SM (occ ~72%).
// ---------------------------------------------------------------------------
__global__ __launch_bounds__(256, 6) void k_attn(float* __restrict__ out)
{
    int bid = blockIdx.x;
    int t  = bid % NTA;
    int h  = (bid / NTA) % H_;
    int b  = bid / (NTA * H_);
    int p0 = t * PTA;
    int tid = threadIdx.x;
    int lane = tid & 31, warp = tid >> 5;

    __shared__ __align__(16) float4 qp4[4][HD_];     // 4-row q groups
    __shared__ __align__(16) float2 probp[8][198];   // prob row pairs (padded)
    __shared__ float  s_inv[PTA];
    __shared__ float  part[4][PTA][HD_];

    const float* qbase = g_qh + (size_t)(b * H_ + h) * P_ * HD_;
    for (int i = tid; i < 4 * HD_; i += 256) {
        int g4 = i >> 6, c = i & 63;
        int r0 = p0 + 4 * g4;
        float x = (r0     < P_) ? qbase[(size_t)r0 * HD_ + c]       : 0.f;
        float y = (r0 + 1 < P_) ? qbase[(size_t)(r0 + 1) * HD_ + c] : 0.f;
        float z = (r0 + 2 < P_) ? qbase[(size_t)(r0 + 2) * HD_ + c] : 0.f;
        float w = (r0 + 3 < P_) ? qbase[(size_t)(r0 + 3) * HD_ + c] : 0.f;
        qp4[g4][c] = make_float4(x, y, z, w);
    }
    __syncthreads();

    // Phase A: logits; thread j = tid (<197), coalesced LDG.32 from khT.
    // Per c: 1 LDG + 4 LDS.128 (broadcast) + 8 FFMA2.
    if (tid < P_) {
        int j = tid;
        const float* khT = g_khT + (size_t)(b * H_ + h) * HD_ * P_;
        ull a[8] = {0ull, 0ull, 0ull, 0ull, 0ull, 0ull, 0ull, 0ull};
#pragma unroll 4
        for (int c = 0; c < HD_; c++) {
            float kv = __ldg(khT + (size_t)c * P_ + j);
            ull s = pack2(kv, kv);
#pragma unroll
            for (int g4 = 0; g4 < 4; g4++) {
                float4 qq = qp4[g4][c];        // LDS.128 broadcast
                a[2 * g4 + 0] = fma2(s, lo2(qq), a[2 * g4 + 0]);
                a[2 * g4 + 1] = fma2(s, hi2(qq), a[2 * g4 + 1]);
            }
        }
#pragma unroll
        for (int pr = 0; pr < 8; pr++) {
            float x, y;
            unpack2(a[pr], x, y);
            probp[pr][j] = make_float2(x * 0.125f, y * 0.125f);
        }
    }
    __syncthreads();

    // Phase B: warp-per-row softmax; each warp does rows warp, warp+8.
    for (int r = warp; r < PTA; r += 8) {
        if (p0 + r >= P_) break;
        int pr = r >> 1, comp = r & 1;
        float vals[7];
        float vmax = -CUDART_INF_F;
#pragma unroll
        for (int tt = 0; tt < 7; tt++) {
            int j = tt * 32 + lane;
            float x = -CUDART_INF_F;
            if (j < P_) x = ((const float*)&probp[pr][j])[comp];
            vals[tt] = x;
            vmax = fmaxf(vmax, x);
        }
#pragma unroll
        for (int o = 16; o; o >>= 1)
            vmax = fmaxf(vmax, __shfl_xor_sync(0xffffffffu, vmax, o));
        float ps = 0.f;
#pragma unroll
        for (int tt = 0; tt < 7; tt++) {
            int j = tt * 32 + lane;
            if (j < P_) {
                float e = expf(vals[tt] - vmax);
                ps += e;
                ((float*)&probp[pr][j])[comp] = e;
            }
        }
#pragma unroll
        for (int o = 16; o; o >>= 1)
            ps += __shfl_xor_sync(0xffffffffu, ps, o);
        if (lane == 0) s_inv[r] = 1.0f / ps;
        __syncwarp();
    }
    __syncthreads();

    // Phase C: AV with contiguous j-range per group; probp read as LDS.128.
    {
        int g = tid >> 6, c = tid & 63;
        int jlo = g * 50;
        int jhi = min(jlo + 50, P_);
        ull acc2[8] = {0ull, 0ull, 0ull, 0ull, 0ull, 0ull, 0ull, 0ull};
        const float* vb = g_vsum + (size_t)(b * H_ + h) * P_ * HD_;
        int j = jlo;
        for (; j + 1 < jhi; j += 2) {
            float va  = __ldg(vb + (size_t)j * HD_ + c);
            float vbv = __ldg(vb + (size_t)(j + 1) * HD_ + c);
            ull v2a = pack2(va, va);
            ull v2b = pack2(vbv, vbv);
#pragma unroll
            for (int pr = 0; pr < 8; pr++) {
                float4 wp = *(const float4*)&probp[pr][j];   // (j, j+1) pairs
                acc2[pr] = fma2(lo2(wp), v2a, acc2[pr]);
                acc2[pr] = fma2(hi2(wp), v2b, acc2[pr]);
            }
        }
        if (j < jhi) {
            float va = __ldg(vb + (size_t)j * HD_ + c);
            ull v2a = pack2(va, va);
#pragma unroll
            for (int pr = 0; pr < 8; pr++) {
                ull w = *(const ull*)&probp[pr][j];
                acc2[pr] = fma2(w, v2a, acc2[pr]);
            }
        }
#pragma unroll
        for (int pr = 0; pr < 8; pr++) {
            float x, y;
            unpack2(acc2[pr], x, y);
            part[g][2 * pr + 0][c] = x;
            part[g][2 * pr + 1][c] = y;
        }
    }
    __syncthreads();

    // epilogue: normalize + write
    for (int rr = tid >> 6; rr < PTA; rr += 4) {
        int cc = tid & 63;
        if (p0 + rr < P_) {
            float s = part[0][rr][cc] + part[1][rr][cc]
                    + part[2][rr][cc] + part[3][rr][cc];
            out[((size_t)b * P_ + p0 + rr) * D_ + h * HD_ + cc] = s * s_inv[rr];
        }
    }
}

// ---------------------------------------------------------------------------
extern "C" void kernel_launch(void* const* d_in, const int* in_sizes, int n_in,
                              void* d_out, int out_size)
{
    const float* q   = (const float*)d_in[0];
    const float* k   = (const float*)d_in[1];
    const float* v   = (const float*)d_in[2];
    const float* wq  = (const float*)d_in[3];
    const float* wk  = (const float*)d_in[4];
    const float* wv  = (const float*)d_in[5];
    const int* idxs  = (const int*)d_in[6];
    float* out = (float*)d_out;

    k_rms<<<B_ * P_, 256>>>(q, k, v, wq, wk, wv);
    k_rep<<<(H_ * NF * HD_ + 255) / 256, 256>>>(idxs);
    k_align<<<B_ * H_ * NT, 256>>>();
    k_attn<<<B_ * H_ * NTA, 256>>>(out);
}